// round 5
// baseline (speedup 1.0000x reference)
#include <cuda_runtime.h>
#include <math.h>
#include <cstdint>

#define HD 2048
#define ID 1408
#define NE 16
#define TK 4
#define NT 1024
#define SID 2816
#define RSCALE 2.5f

// ---------------- scratch ----------------
__device__ int   d_cnt[NE];
__device__ int   d_tok[NE * NT];
__device__ float d_wt [NE * NT];
__device__ float d_hbuf[NE * NT * ID];
__device__ float d_hsh [NT * SID];

// ---------------- helpers ----------------
__device__ __forceinline__ uint32_t f2tf(float f) {
    uint32_t r;
    asm("cvt.rna.tf32.f32 %0, %1;" : "=r"(r) : "f"(f));
    return r;
}
__device__ __forceinline__ void mma8(float* c, const uint32_t* a, const uint32_t* b) {
    asm volatile(
        "mma.sync.aligned.m16n8k8.row.col.f32.tf32.tf32.f32 "
        "{%0,%1,%2,%3}, {%4,%5,%6,%7}, {%8,%9}, {%0,%1,%2,%3};"
        : "+f"(c[0]), "+f"(c[1]), "+f"(c[2]), "+f"(c[3])
        : "r"(a[0]), "r"(a[1]), "r"(a[2]), "r"(a[3]), "r"(b[0]), "r"(b[1]));
}
__device__ __forceinline__ float silu(float g) { return g / (1.f + __expf(-g)); }

// permuted-K tf32 smem: row stride 24 u32 (96B), K=16 per stage stored as
// positions [c0,c4,c1,c5,c2,c6,c3,c7 | c8,c12,c9,c13,c10,c14,c11,c15]
#define SROW 24
// cvt + permuted store of one (row, k-half): v0..v3 = cols 8h..8h+3, v4..7 = 8h+4..
__device__ __forceinline__ void sts_perm(uint32_t* d, float4 lo, float4 hi) {
    uint4 p0 = { f2tf(lo.x), f2tf(hi.x), f2tf(lo.y), f2tf(hi.y) };
    uint4 p1 = { f2tf(lo.z), f2tf(hi.z), f2tf(lo.w), f2tf(hi.w) };
    *(uint4*)d       = p0;
    *(uint4*)(d + 4) = p1;
}

// ---------------- init / memset ----------------
__global__ void init_kernel() {
    if (threadIdx.x < NE) d_cnt[threadIdx.x] = 0;
}
__global__ void zero_out(float4* out) {
    out[blockIdx.x * 256 + threadIdx.x] = make_float4(0.f, 0.f, 0.f, 0.f);
}

// ---------------- gate ----------------
__global__ void gate_kernel(const float* __restrict__ x,
                            const float* __restrict__ gw,
                            const float* __restrict__ gb) {
    const int t = blockIdx.x;
    __shared__ float s_sc[NE];
    const int wid = threadIdx.x >> 5;
    const int lane = threadIdx.x & 31;
    const float* xr = x + (size_t)t * HD;
    const float* wr = gw + (size_t)wid * HD;
    float acc = 0.f;
    for (int k = lane; k < HD; k += 32) acc += xr[k] * wr[k];
    #pragma unroll
    for (int o = 16; o; o >>= 1) acc += __shfl_xor_sync(0xffffffffu, acc, o);
    if (lane == 0) s_sc[wid] = 1.f / (1.f + expf(-acc)) + gb[wid];
    __syncthreads();
    if (threadIdx.x != 0) return;

    float sc[NE];
    #pragma unroll
    for (int e = 0; e < NE; e++) sc[e] = s_sc[e];
    float gs[4];
    #pragma unroll
    for (int g = 0; g < 4; g++) {
        float m = sc[g * 4];
        #pragma unroll
        for (int j = 1; j < 4; j++) m = fmaxf(m, sc[g * 4 + j]);
        gs[g] = m;
    }
    int g0 = 0;
    for (int g = 1; g < 4; g++) if (gs[g] > gs[g0]) g0 = g;
    int g1 = -1;
    for (int g = 0; g < 4; g++) {
        if (g == g0) continue;
        if (g1 < 0 || gs[g] > gs[g1]) g1 = g;
    }
    float masked[NE];
    #pragma unroll
    for (int e = 0; e < NE; e++) {
        int g = e >> 2;
        masked[e] = (g == g0 || g == g1) ? sc[e] : 0.f;
    }
    int idx[TK]; float w[TK]; bool used[NE];
    #pragma unroll
    for (int e = 0; e < NE; e++) used[e] = false;
    float wsum = 0.f;
    for (int k = 0; k < TK; k++) {
        int best = -1;
        for (int e = 0; e < NE; e++) {
            if (used[e]) continue;
            if (best < 0 || masked[e] > masked[best]) best = e;
        }
        used[best] = true;
        idx[k] = best; w[k] = masked[best]; wsum += masked[best];
    }
    const float inv = 1.f / (wsum + 1e-6f);
    for (int k = 0; k < TK; k++) {
        int e = idx[k];
        int pos = atomicAdd(&d_cnt[e], 1);
        d_tok[e * NT + pos] = t;
        d_wt [e * NT + pos] = w[k] * inv * RSCALE;
    }
}

// ---------------- GEMM1: routed (z<16) + shared (z==16), dual gate/up ------
// Tile 128M x 64N dual, Kc=16, 2-stage register-staged double buffer.
// smem u32 layout per stage (6144 u32): A[128*24] | G[64*24] | U[64*24]
#define G1_STAGE_U32 6144
#define G1_SMEM (512 + 2 * G1_STAGE_U32 * 4)
__global__ void __launch_bounds__(256, 2)
gemm1_mma(const float* __restrict__ X,
          const float* __restrict__ Wg_r, const float* __restrict__ Wu_r,
          const float* __restrict__ Wg_s, const float* __restrict__ Wu_s,
          float* __restrict__ Hr, float* __restrict__ Hs) {
    const int e = blockIdx.z;
    const bool SHARED = (e == NE);
    int M, ldH, ntile;
    const float *Wg, *Wu; float* Ho;
    if (SHARED) {
        M = NT; ldH = SID; ntile = SID / 64;
        Wg = Wg_s; Wu = Wu_s; Ho = Hs;
    } else {
        M = d_cnt[e]; ldH = ID; ntile = ID / 64;
        Wg = Wg_r + (size_t)e * ID * HD;
        Wu = Wu_r + (size_t)e * ID * HD;
        Ho = Hr + (size_t)e * NT * ID;
    }
    if ((int)blockIdx.x >= ntile) return;
    const int m0 = blockIdx.y * 128;
    if (m0 >= M) return;
    const int n0 = blockIdx.x * 64;

    extern __shared__ char smem[];
    int* s_tok = (int*)smem;
    uint32_t* ST = (uint32_t*)(smem + 512);
    const int tid = threadIdx.x, lane = tid & 31, wid = tid >> 5;
    const int wr = wid >> 2, wc = wid & 3;
    const int l4 = lane >> 2, lm = lane & 3;
    if (!SHARED && tid < 128) s_tok[tid] = (m0 + tid < M) ? d_tok[e * NT + m0 + tid] : 0;
    __syncthreads();

    // loader geometry: A(row=tid>>1, h=tid&1); W: tid<128 -> G, else -> U
    const int ra = tid >> 1, h = tid & 1;
    const bool aok = (m0 + ra) < M;
    int arow;
    if (SHARED) arow = aok ? m0 + ra : 0;
    else        arow = aok ? s_tok[ra] : 0;
    const float4* Ap = (const float4*)(X + (size_t)arow * HD) + 2 * h;
    const int rw = (tid < 128) ? (tid >> 1) : ((tid - 128) >> 1);
    const float4* Wp = (const float4*)(((tid < 128) ? Wg : Wu) + (size_t)(n0 + rw) * HD) + 2 * h;
    uint32_t* dA0 = ST + ra * SROW + 8 * h;
    uint32_t* dW0 = ST + ((tid < 128) ? 3072 : 4608) + rw * SROW + 8 * h;

    float4 A0, A1, W0, W1;
    const float4 Z = make_float4(0.f, 0.f, 0.f, 0.f);
    auto ldg = [&](int c) {
        A0 = aok ? Ap[c * 4] : Z;
        A1 = aok ? Ap[c * 4 + 1] : Z;
        W0 = Wp[c * 4];
        W1 = Wp[c * 4 + 1];
    };
    auto sts = [&](int buf) {
        sts_perm(dA0 + buf * G1_STAGE_U32, A0, A1);
        sts_perm(dW0 + buf * G1_STAGE_U32, W0, W1);
    };

    const uint32_t a_off = (uint32_t)((wr * 64 + l4) * SROW + 2 * lm);
    const uint32_t g_off = (uint32_t)(3072 + (wc * 16 + l4) * SROW + 2 * lm);

    float cg[4][2][4] = {}, cu[4][2][4] = {};
    const int C = HD >> 4;
    ldg(0); sts(0); ldg(1);
    __syncthreads();

    #pragma unroll 1
    for (int c = 0; c < C; c++) {
        const uint32_t* sa = ST + (c & 1) * G1_STAGE_U32 + a_off;
        const uint32_t* sg = ST + (c & 1) * G1_STAGE_U32 + g_off;
        const uint32_t* su = sg + 1536;
        #pragma unroll
        for (int ks = 0; ks < 2; ks++) {
            uint32_t a[4][4];
            #pragma unroll
            for (int mi = 0; mi < 4; mi++) {
                uint2 p = *(const uint2*)(sa + mi * 384 + ks * 8);
                uint2 q = *(const uint2*)(sa + mi * 384 + 192 + ks * 8);
                a[mi][0] = p.x; a[mi][1] = q.x; a[mi][2] = p.y; a[mi][3] = q.y;
            }
            #pragma unroll
            for (int ni = 0; ni < 2; ni++) {
                uint2 pg = *(const uint2*)(sg + ni * 192 + ks * 8);
                uint2 pu = *(const uint2*)(su + ni * 192 + ks * 8);
                uint32_t bg[2] = { pg.x, pg.y };
                uint32_t bu[2] = { pu.x, pu.y };
                #pragma unroll
                for (int mi = 0; mi < 4; mi++) {
                    mma8(cg[mi][ni], a[mi], bg);
                    mma8(cu[mi][ni], a[mi], bu);
                }
            }
        }
        if (c + 1 < C) {
            __syncthreads();
            sts((c + 1) & 1);
            if (c + 2 < C) ldg(c + 2);
            __syncthreads();
        }
    }
    #pragma unroll
    for (int mi = 0; mi < 4; mi++)
        #pragma unroll
        for (int ni = 0; ni < 2; ni++) {
            const int r = m0 + wr * 64 + mi * 16 + l4;
            const int cc = n0 + wc * 16 + ni * 8 + 2 * lm;
            if (r < M) {
                float2 v = { silu(cg[mi][ni][0]) * cu[mi][ni][0],
                             silu(cg[mi][ni][1]) * cu[mi][ni][1] };
                *(float2*)(Ho + (size_t)r * ldH + cc) = v;
            }
            if (r + 8 < M) {
                float2 v = { silu(cg[mi][ni][2]) * cu[mi][ni][2],
                             silu(cg[mi][ni][3]) * cu[mi][ni][3] };
                *(float2*)(Ho + (size_t)(r + 8) * ldH + cc) = v;
            }
        }
}

// ---------------- GEMM2: down, routed (z<16) + shared (z==16) --------------
// Tile 128M x 128N, Kc=16, 2-stage; smem per stage: A[128*24] | B[128*24]
#define G2_STAGE_U32 6144
#define G2_SMEM (1024 + 2 * G2_STAGE_U32 * 4)
__global__ void __launch_bounds__(256, 2)
gemm2_mma(const float* __restrict__ Hr, const float* __restrict__ Wd_r,
          const float* __restrict__ Hs, const float* __restrict__ Wd_s,
          float* __restrict__ Out) {
    const int e = blockIdx.z;
    const bool SHARED = (e == NE);
    int M, K;
    const float *Hin, *Wd;
    if (SHARED) {
        M = NT; K = SID; Hin = Hs; Wd = Wd_s;
    } else {
        M = d_cnt[e]; K = ID;
        Hin = Hr + (size_t)e * NT * ID;
        Wd  = Wd_r + (size_t)e * HD * ID;
    }
    const int m0 = blockIdx.y * 128;
    if (m0 >= M) return;
    const int n0 = blockIdx.x * 128;

    extern __shared__ char smem[];
    int*   s_tok = (int*)smem;
    float* s_wt  = (float*)(smem + 512);
    uint32_t* ST = (uint32_t*)(smem + 1024);
    const int tid = threadIdx.x, lane = tid & 31, wid = tid >> 5;
    const int wr = wid >> 2, wc = wid & 3;
    const int l4 = lane >> 2, lm = lane & 3;
    if (tid < 128) {
        const bool ok = m0 + tid < M;
        if (SHARED) { s_tok[tid] = ok ? m0 + tid : 0; s_wt[tid] = 1.f; }
        else {
            s_tok[tid] = ok ? d_tok[e * NT + m0 + tid] : 0;
            s_wt [tid] = ok ? d_wt [e * NT + m0 + tid] : 0.f;
        }
    }
    __syncthreads();

    const int ra = tid >> 1, h = tid & 1;
    const bool aok = (m0 + ra) < M;
    const float4* Ap = (const float4*)(Hin + (size_t)(aok ? m0 + ra : 0) * K) + 2 * h;
    const float4* Bp = (const float4*)(Wd + (size_t)(n0 + ra) * K) + 2 * h;
    uint32_t* dA0 = ST + ra * SROW + 8 * h;
    uint32_t* dB0 = ST + 3072 + ra * SROW + 8 * h;

    float4 A0, A1, B0, B1;
    const float4 Z = make_float4(0.f, 0.f, 0.f, 0.f);
    auto ldg = [&](int c) {
        A0 = aok ? Ap[c * 4] : Z;
        A1 = aok ? Ap[c * 4 + 1] : Z;
        B0 = Bp[c * 4];
        B1 = Bp[c * 4 + 1];
    };
    auto sts = [&](int buf) {
        sts_perm(dA0 + buf * G2_STAGE_U32, A0, A1);
        sts_perm(dB0 + buf * G2_STAGE_U32, B0, B1);
    };

    const uint32_t a_off = (uint32_t)((wr * 64 + l4) * SROW + 2 * lm);
    const uint32_t b_off = (uint32_t)(3072 + (wc * 32 + l4) * SROW + 2 * lm);

    float acc[4][4][4] = {};
    const int C = K >> 4;
    ldg(0); sts(0); ldg(1);
    __syncthreads();

    #pragma unroll 1
    for (int c = 0; c < C; c++) {
        const uint32_t* sa = ST + (c & 1) * G2_STAGE_U32 + a_off;
        const uint32_t* sb = ST + (c & 1) * G2_STAGE_U32 + b_off;
        #pragma unroll
        for (int ks = 0; ks < 2; ks++) {
            uint32_t a[4][4];
            #pragma unroll
            for (int mi = 0; mi < 4; mi++) {
                uint2 p = *(const uint2*)(sa + mi * 384 + ks * 8);
                uint2 q = *(const uint2*)(sa + mi * 384 + 192 + ks * 8);
                a[mi][0] = p.x; a[mi][1] = q.x; a[mi][2] = p.y; a[mi][3] = q.y;
            }
            #pragma unroll
            for (int ni = 0; ni < 4; ni++) {
                uint2 pb = *(const uint2*)(sb + ni * 192 + ks * 8);
                uint32_t b[2] = { pb.x, pb.y };
                #pragma unroll
                for (int mi = 0; mi < 4; mi++)
                    mma8(acc[mi][ni], a[mi], b);
            }
        }
        if (c + 1 < C) {
            __syncthreads();
            sts((c + 1) & 1);
            if (c + 2 < C) ldg(c + 2);
            __syncthreads();
        }
    }
    #pragma unroll
    for (int mi = 0; mi < 4; mi++) {
        const int rl0 = wr * 64 + mi * 16 + l4;
        #pragma unroll
        for (int ni = 0; ni < 4; ni++) {
            const int cc = n0 + wc * 32 + ni * 8 + 2 * lm;
            #pragma unroll
            for (int hh = 0; hh < 2; hh++) {
                const int rl = rl0 + hh * 8;
                if (m0 + rl >= M) continue;
                const float w = s_wt[rl];
                float* o = Out + (size_t)s_tok[rl] * HD + cc;
                atomicAdd(o + 0, w * acc[mi][ni][2 * hh + 0]);
                atomicAdd(o + 1, w * acc[mi][ni][2 * hh + 1]);
            }
        }
    }
}

// ---------------- launch ----------------
extern "C" void kernel_launch(void* const* d_in, const int* in_sizes, int n_in,
                              void* d_out, int out_size) {
    const float* x       = (const float*)d_in[0];
    const float* gate_w  = (const float*)d_in[1];
    const float* gate_b  = (const float*)d_in[2];
    const float* w_gate  = (const float*)d_in[3];
    const float* w_up    = (const float*)d_in[4];
    const float* w_down  = (const float*)d_in[5];
    const float* sw_gate = (const float*)d_in[6];
    const float* sw_up   = (const float*)d_in[7];
    const float* sw_down = (const float*)d_in[8];
    float* out = (float*)d_out;

    float* hbuf; cudaGetSymbolAddress((void**)&hbuf, d_hbuf);
    float* hsh;  cudaGetSymbolAddress((void**)&hsh,  d_hsh);

    cudaFuncSetAttribute(gemm1_mma, cudaFuncAttributeMaxDynamicSharedMemorySize, G1_SMEM);
    cudaFuncSetAttribute(gemm2_mma, cudaFuncAttributeMaxDynamicSharedMemorySize, G2_SMEM);

    zero_out<<<(NT * HD) / 1024, 256>>>((float4*)out);
    init_kernel<<<1, 32>>>();
    gate_kernel<<<NT, 512>>>(x, gate_w, gate_b);

    gemm1_mma<<<dim3(SID / 64, NT / 128, NE + 1), 256, G1_SMEM>>>(
        x, w_gate, w_up, sw_gate, sw_up, hbuf, hsh);
    gemm2_mma<<<dim3(HD / 128, NT / 128, NE + 1), 256, G2_SMEM>>>(
        hbuf, w_down, hsh, sw_down, out);
}